// round 2
// baseline (speedup 1.0000x reference)
#include <cuda_runtime.h>
#include <math.h>
#include <stdint.h>

#define B_   64
#define T_   256
#define ID_  512
#define HD_  1024
#define G4_  4096   // 4*HD

#define NB      128          // persistent blocks (each owns 8 hidden units)
#define JPB     8            // hidden units per block (1024/128)
#define KT      64           // K-chunk of h staged in smem per iteration
#define THREADS2 256
#define SMEM2_BYTES (1024*32*4 + KT*64*4)   // Wsm (128KB) + hs (16KB) = 147456

// Scratch: gates_x laid out [t][n][b] so step-t reads are fully coalesced.
__device__ float g_gx[(size_t)T_ * G4_ * B_];   // 256 MB, static (allowed)
__device__ unsigned int g_bar_count = 0;
__device__ unsigned int g_bar_gen   = 0;

// ---------------------------------------------------------------------------
// Phase 1: gx[t][n][b] = sum_k x[b][t][k] * Wi[k][n] + bi[n] + bh[n]
// grid: (4H/64, T/64, B), block 256, 64x64 tile, 4x4 micro-tile
// ---------------------------------------------------------------------------
__global__ void gemm_x_kernel(const float* __restrict__ x,
                              const float* __restrict__ Wi,
                              const float* __restrict__ bi,
                              const float* __restrict__ bh) {
    __shared__ float xs[16][64];   // [k][t]
    __shared__ float ws[16][64];   // [k][n]

    const int b  = blockIdx.z;
    const int t0 = blockIdx.y * 64;
    const int n0 = blockIdx.x * 64;
    const int tid = threadIdx.x;
    const int tm = tid & 15;       // t micro-row group (4 t's)
    const int tn = tid >> 4;       // n micro-col group (4 n's)

    float acc[4][4];
#pragma unroll
    for (int i = 0; i < 4; i++)
#pragma unroll
        for (int jq = 0; jq < 4; jq++) acc[i][jq] = 0.0f;

    const float* xb = x + ((long)b * T_ + t0) * ID_;

    for (int k0 = 0; k0 < ID_; k0 += 16) {
        // load x tile transposed -> xs[k][t]
        {
            int i  = tid >> 2;      // 0..63 (t row)
            int kq = tid & 3;       // 0..3
            float4 v = *(const float4*)(xb + (long)i * ID_ + k0 + 4 * kq);
            xs[4 * kq + 0][i] = v.x;
            xs[4 * kq + 1][i] = v.y;
            xs[4 * kq + 2][i] = v.z;
            xs[4 * kq + 3][i] = v.w;
        }
        // load Wi tile -> ws[k][n]
        {
            int r  = tid >> 4;      // 0..15
            int nq = tid & 15;      // 0..15
            float4 v = *(const float4*)(Wi + (long)(k0 + r) * G4_ + n0 + 4 * nq);
            *(float4*)&ws[r][4 * nq] = v;
        }
        __syncthreads();
#pragma unroll
        for (int k = 0; k < 16; k++) {
            float4 a = *(float4*)&xs[k][4 * tm];
            float4 w = *(float4*)&ws[k][4 * tn];
            acc[0][0] = fmaf(a.x, w.x, acc[0][0]);
            acc[0][1] = fmaf(a.x, w.y, acc[0][1]);
            acc[0][2] = fmaf(a.x, w.z, acc[0][2]);
            acc[0][3] = fmaf(a.x, w.w, acc[0][3]);
            acc[1][0] = fmaf(a.y, w.x, acc[1][0]);
            acc[1][1] = fmaf(a.y, w.y, acc[1][1]);
            acc[1][2] = fmaf(a.y, w.z, acc[1][2]);
            acc[1][3] = fmaf(a.y, w.w, acc[1][3]);
            acc[2][0] = fmaf(a.z, w.x, acc[2][0]);
            acc[2][1] = fmaf(a.z, w.y, acc[2][1]);
            acc[2][2] = fmaf(a.z, w.z, acc[2][2]);
            acc[2][3] = fmaf(a.z, w.w, acc[2][3]);
            acc[3][0] = fmaf(a.w, w.x, acc[3][0]);
            acc[3][1] = fmaf(a.w, w.y, acc[3][1]);
            acc[3][2] = fmaf(a.w, w.z, acc[3][2]);
            acc[3][3] = fmaf(a.w, w.w, acc[3][3]);
        }
        __syncthreads();
    }

#pragma unroll
    for (int i = 0; i < 4; i++) {
        int t = t0 + 4 * tm + i;
#pragma unroll
        for (int jq = 0; jq < 4; jq++) {
            int n = n0 + 4 * tn + jq;
            float bias = __ldg(bi + n) + __ldg(bh + n);
            g_gx[(size_t)t * (G4_ * B_) + (size_t)n * B_ + b] = acc[i][jq] + bias;
        }
    }
}

// ---------------------------------------------------------------------------
// Phase 2: persistent recurrent kernel. Each block owns JPB=8 hidden units
// (all 4 gates) for all 64 batches. Wh slice lives in SMEM across all steps.
// ---------------------------------------------------------------------------
__device__ __forceinline__ float sigf(float v) {
    return 1.0f / (1.0f + expf(-v));
}

__device__ __forceinline__ void grid_barrier() {
    __syncthreads();
    if (threadIdx.x == 0) {
        __threadfence();
        unsigned gen = atomicAdd(&g_bar_gen, 0u);
        unsigned arrived = atomicAdd(&g_bar_count, 1u);
        if (arrived == NB - 1) {
            atomicExch(&g_bar_count, 0u);
            __threadfence();
            atomicAdd(&g_bar_gen, 1u);
        } else {
            while (atomicAdd(&g_bar_gen, 0u) == gen) { __nanosleep(128); }
        }
        __threadfence();
    }
    __syncthreads();
}

extern __shared__ float smem2[];

__global__ void lstm_seq_kernel(const float* __restrict__ Wh,
                                float* __restrict__ out) {
    float* Wsm = smem2;                 // [k][jj][g]: k*32 + jj*4 + g (128 KB)
    float* hs  = smem2 + 1024 * 32;     // [kk][b] (16 KB)

    const int bid  = blockIdx.x;
    const int tid  = threadIdx.x;
    const int bIdx = tid & 31;          // batch group: 2 batches each
    const int jIdx = tid >> 5;          // 0..7
    const int j0   = bid * JPB;
    const int j    = j0 + jIdx;

    float* Q  = out;                               // [B][T][HD]
    float* hT = out + (size_t)B_ * T_ * HD_;
    float* cT = hT + (size_t)B_ * HD_;

    // Load this block's Wh slice into SMEM once (reused 255 times).
    for (int idx = tid; idx < 1024 * 32; idx += THREADS2) {
        int k  = idx >> 5;
        int r  = idx & 31;
        int jj = r >> 2;
        int g  = r & 3;
        Wsm[idx] = Wh[(long)k * G4_ + g * HD_ + j0 + jj];
    }
    __syncthreads();

    float cr0 = 0.0f, cr1 = 0.0f;

    for (int t = 0; t < T_; t++) {
        // init accumulators from gates_x (bias already folded in)
        const float* gxt = g_gx + (size_t)t * (G4_ * B_);
        float2 vf = *(const float2*)(gxt + ((size_t)(0 * HD_ + j)) * B_ + 2 * bIdx);
        float2 vi = *(const float2*)(gxt + ((size_t)(1 * HD_ + j)) * B_ + 2 * bIdx);
        float2 va = *(const float2*)(gxt + ((size_t)(2 * HD_ + j)) * B_ + 2 * bIdx);
        float2 vo = *(const float2*)(gxt + ((size_t)(3 * HD_ + j)) * B_ + 2 * bIdx);
        float af0 = vf.x, af1 = vf.y;
        float ai0 = vi.x, ai1 = vi.y;
        float aa0 = va.x, aa1 = va.y;
        float ao0 = vo.x, ao1 = vo.y;

        if (t > 0) {
            for (int kc = 0; kc < HD_; kc += KT) {
                __syncthreads();
                // stage h(t-1)[b][kc..kc+KT) transposed -> hs[kk][b]
                {
                    int bb = tid & 63;
                    int ms = tid >> 6;   // 0..3
                    const float* hb = Q + ((long)bb * T_ + (t - 1)) * HD_ + kc;
#pragma unroll
                    for (int m = ms; m < KT / 4; m += 4) {
                        float4 v = *(const float4*)(hb + 4 * m);
                        hs[(4 * m + 0) * 64 + bb] = v.x;
                        hs[(4 * m + 1) * 64 + bb] = v.y;
                        hs[(4 * m + 2) * 64 + bb] = v.z;
                        hs[(4 * m + 3) * 64 + bb] = v.w;
                    }
                }
                __syncthreads();
                const float* Wp = Wsm + kc * 32 + jIdx * 4;
#pragma unroll
                for (int kk = 0; kk < KT; kk++) {
                    float2 hv = *(const float2*)(hs + (kk << 6) + 2 * bIdx);
                    float4 wv = *(const float4*)(Wp + (kk << 5));
                    af0 = fmaf(hv.x, wv.x, af0);
                    af1 = fmaf(hv.y, wv.x, af1);
                    ai0 = fmaf(hv.x, wv.y, ai0);
                    ai1 = fmaf(hv.y, wv.y, ai1);
                    aa0 = fmaf(hv.x, wv.z, aa0);
                    aa1 = fmaf(hv.y, wv.z, aa1);
                    ao0 = fmaf(hv.x, wv.w, ao0);
                    ao1 = fmaf(hv.y, wv.w, ao1);
                }
            }
        }

        // elementwise gates for 2 batches
        {
            float f = sigf(af0), ig = sigf(ai0), a = tanhf(aa0), o = sigf(ao0);
            cr0 = f * cr0 + ig * a;
            float hv = o * tanhf(cr0);
            int b = 2 * bIdx + 0;
            Q[((long)b * T_ + t) * HD_ + j] = hv;
            if (t == T_ - 1) { hT[(long)b * HD_ + j] = hv; cT[(long)b * HD_ + j] = cr0; }
        }
        {
            float f = sigf(af1), ig = sigf(ai1), a = tanhf(aa1), o = sigf(ao1);
            cr1 = f * cr1 + ig * a;
            float hv = o * tanhf(cr1);
            int b = 2 * bIdx + 1;
            Q[((long)b * T_ + t) * HD_ + j] = hv;
            if (t == T_ - 1) { hT[(long)b * HD_ + j] = hv; cT[(long)b * HD_ + j] = cr1; }
        }

        if (t < T_ - 1) grid_barrier();
    }
}

// ---------------------------------------------------------------------------
extern "C" void kernel_launch(void* const* d_in, const int* in_sizes, int n_in,
                              void* d_out, int out_size) {
    (void)in_sizes; (void)n_in; (void)out_size;
    const float* x  = (const float*)d_in[0];
    const float* Wi = (const float*)d_in[1];
    const float* bi = (const float*)d_in[2];
    const float* Wh = (const float*)d_in[3];
    const float* bh = (const float*)d_in[4];
    float* out = (float*)d_out;

    cudaFuncSetAttribute(lstm_seq_kernel,
                         cudaFuncAttributeMaxDynamicSharedMemorySize, SMEM2_BYTES);

    dim3 g1(G4_ / 64, T_ / 64, B_);
    gemm_x_kernel<<<g1, 256>>>(x, Wi, bi, bh);
    lstm_seq_kernel<<<NB, THREADS2, SMEM2_BYTES>>>(Wh, out);
}